// round 6
// baseline (speedup 1.0000x reference)
#include <cuda_runtime.h>
#include <cstdint>

// ESN: out[b,p,l], elementwise-diagonal recurrence.
// B=32, D_IN=64, D_STATE=1024, L=2048, LEAK=0.5
// v5: software-pipelined — dots(c+1) source-interleaved with scan(c) so the
//     44-cyc/step x-chain hides under the next chunk's FMA/LDS issue stream.
#define BB 32
#define DIN 64
#define DST 1024
#define LL 2048
#define TT 32
#define PTILE 128
#define NCH (LL / TT)

__device__ __forceinline__ unsigned long long pack2(float a, float b) {
    unsigned long long r;
    asm("mov.b64 %0,{%1,%2};" : "=l"(r) : "f"(a), "f"(b));
    return r;
}
__device__ __forceinline__ void unpack2(unsigned long long v, float& a, float& b) {
    asm("mov.b64 {%0,%1},%2;" : "=f"(a), "=f"(b) : "l"(v));
}
__device__ __forceinline__ void ffma2(unsigned long long& acc,
                                      unsigned long long a, unsigned long long b) {
    asm("fma.rn.f32x2 %0,%1,%2,%0;" : "+l"(acc) : "l"(a), "l"(b));
}
__device__ __forceinline__ unsigned long long fadd2(unsigned long long a,
                                                    unsigned long long b) {
    unsigned long long r;
    asm("add.rn.f32x2 %0,%1,%2;" : "=l"(r) : "l"(a), "l"(b));
    return r;
}
__device__ __forceinline__ float ex2f(float v) {
    float r; asm("ex2.approx.f32 %0,%1;" : "=f"(r) : "f"(v)); return r;
}
__device__ __forceinline__ float rcpf(float v) {
    float r; asm("rcp.approx.f32 %0,%1;" : "=f"(r) : "f"(v)); return r;
}

__global__ __launch_bounds__(PTILE, 2) void esn_kernel(
    const float* __restrict__ u,      // [B, DIN, L]
    const float* __restrict__ w_in,   // [DST, DIN]
    const float* __restrict__ w_hh,   // [DST, DST] (diagonal used)
    const float* __restrict__ bias,   // [DST]
    float* __restrict__ out)          // [B, DST, L]
{
    __shared__ __align__(16) float su[2][TT][68];        // double-buffered [t][h]
    __shared__ __align__(16) float tile[PTILE][TT + 4];  // 144B row stride

    const int tid = threadIdx.x;
    const int b   = blockIdx.y;
    const int p0  = blockIdx.x * PTILE;
    const int p   = p0 + tid;

    // tanh via base-2:  x' = fma(0.5,x,0.5) - rcp(ex2(pre2)+1)
    // pre2 = K2*(dot + bias + d*x);  K2 folded into W2, b2, d2.
    const float K2 = 2.8853900817779268f;   // 2*log2(e)

    unsigned long long W2[DIN / 2];
    const float4* wrow = (const float4*)(w_in + (size_t)p * DIN);
#pragma unroll
    for (int i = 0; i < DIN / 4; i++) {
        float4 v = wrow[i];
        W2[2 * i]     = pack2(v.x * K2, v.y * K2);
        W2[2 * i + 1] = pack2(v.z * K2, v.w * K2);
    }
    const float d2 = w_hh[(size_t)p * DST + p] * K2;
    const float b2 = bias[p] * K2;

    const float* ub = u + (size_t)b * DIN * LL;
    float*       ob = out + ((size_t)b * DST + p0) * LL;

    // staging geometry: 4 float4 per thread cover 64h x 32l
    const int h0 = (tid + 0 * PTILE) >> 3, t0 = ((tid + 0 * PTILE) & 7) << 2;
    const int h1 = (tid + 1 * PTILE) >> 3, t1 = ((tid + 1 * PTILE) & 7) << 2;
    const int h2 = (tid + 2 * PTILE) >> 3, t2 = ((tid + 2 * PTILE) & 7) << 2;
    const int h3 = (tid + 3 * PTILE) >> 3, t3 = ((tid + 3 * PTILE) & 7) << 2;

    const int orow = tid >> 3;              // output transpose geometry
    const int ocol = (tid & 7) << 2;

    float4 g0, g1, g2, g3;

    // ---------------- macros (NOT functions: keep arrays in regs) ----------
#define PREFETCH(L0)                                                          \
    {   const float* un = ub + (size_t)(L0);                                  \
        g0 = *(const float4*)(un + (size_t)h0 * LL + t0);                     \
        g1 = *(const float4*)(un + (size_t)h1 * LL + t1);                     \
        g2 = *(const float4*)(un + (size_t)h2 * LL + t2);                     \
        g3 = *(const float4*)(un + (size_t)h3 * LL + t3); }

#define STAGE(BUF)                                                            \
    {   su[BUF][t0+0][h0]=g0.x; su[BUF][t0+1][h0]=g0.y;                       \
        su[BUF][t0+2][h0]=g0.z; su[BUF][t0+3][h0]=g0.w;                       \
        su[BUF][t1+0][h1]=g1.x; su[BUF][t1+1][h1]=g1.y;                       \
        su[BUF][t1+2][h1]=g1.z; su[BUF][t1+3][h1]=g1.w;                       \
        su[BUF][t2+0][h2]=g2.x; su[BUF][t2+1][h2]=g2.y;                       \
        su[BUF][t2+2][h2]=g2.z; su[BUF][t2+3][h2]=g2.w;                       \
        su[BUF][t3+0][h3]=g3.x; su[BUF][t3+1][h3]=g3.y;                       \
        su[BUF][t3+2][h3]=g3.z; su[BUF][t3+3][h3]=g3.w; }

#define DOT_T(BUF, T, OUTV)                                                   \
    {   const ulonglong2* s = (const ulonglong2*)(&su[BUF][T][0]);            \
        ulonglong2 v0=s[0], v1=s[1], v2=s[2], v3=s[3];                        \
        ulonglong2 v4=s[4], v5=s[5], v6=s[6], v7=s[7];                        \
        ulonglong2 v8=s[8], v9=s[9], vA=s[10],vB=s[11];                       \
        ulonglong2 vC=s[12],vD=s[13],vE=s[14],vF=s[15];                       \
        unsigned long long a0 = pack2(b2, 0.0f), a1=0ull, a2=0ull, a3=0ull;   \
        ffma2(a0,W2[0], v0.x); ffma2(a1,W2[1], v0.y);                         \
        ffma2(a2,W2[2], v1.x); ffma2(a3,W2[3], v1.y);                         \
        ffma2(a0,W2[4], v2.x); ffma2(a1,W2[5], v2.y);                         \
        ffma2(a2,W2[6], v3.x); ffma2(a3,W2[7], v3.y);                         \
        ffma2(a0,W2[8], v4.x); ffma2(a1,W2[9], v4.y);                         \
        ffma2(a2,W2[10],v5.x); ffma2(a3,W2[11],v5.y);                         \
        ffma2(a0,W2[12],v6.x); ffma2(a1,W2[13],v6.y);                         \
        ffma2(a2,W2[14],v7.x); ffma2(a3,W2[15],v7.y);                         \
        ffma2(a0,W2[16],v8.x); ffma2(a1,W2[17],v8.y);                         \
        ffma2(a2,W2[18],v9.x); ffma2(a3,W2[19],v9.y);                         \
        ffma2(a0,W2[20],vA.x); ffma2(a1,W2[21],vA.y);                         \
        ffma2(a2,W2[22],vB.x); ffma2(a3,W2[23],vB.y);                         \
        ffma2(a0,W2[24],vC.x); ffma2(a1,W2[25],vC.y);                         \
        ffma2(a2,W2[26],vD.x); ffma2(a3,W2[27],vD.y);                         \
        ffma2(a0,W2[28],vE.x); ffma2(a1,W2[29],vE.y);                         \
        ffma2(a2,W2[30],vF.x); ffma2(a3,W2[31],vF.y);                         \
        unsigned long long asum = fadd2(fadd2(a0,a1), fadd2(a2,a3));          \
        float lo_, hi_; unpack2(asum, lo_, hi_);                              \
        OUTV = lo_ + hi_; }

#define SCAN_T(PRE, T)                                                        \
    {   float p2_ = fmaf(d2, x, PRE[T]);                                      \
        float e_  = ex2f(p2_);                                                \
        float r_  = rcpf(e_ + 1.0f);                                          \
        x = fmaf(0.5f, x, 0.5f) - r_;                                         \
        PRE[T] = x; }

#define STORE_TILE(PRE)                                                       \
    _Pragma("unroll")                                                         \
    for (int k = 0; k < TT / 4; k++)                                          \
        *(float4*)&tile[tid][4*k] =                                           \
            make_float4(PRE[4*k], PRE[4*k+1], PRE[4*k+2], PRE[4*k+3]);

#define OUTPUT(L0)                                                            \
    _Pragma("unroll")                                                         \
    for (int it = 0; it < 8; it++) {                                          \
        int row_ = orow + it * 16;                                            \
        float4 v_ = *(const float4*)&tile[row_][ocol];                        \
        *(float4*)(ob + (size_t)row_ * LL + (L0) + ocol) = v_; }

    // ---------------- prologue --------------------------------------------
    PREFETCH(0);
    STAGE(0);
    __syncthreads();
    PREFETCH(TT);                    // chunk 1 into regs

    float preA[TT], preB[TT];
    float x = 0.0f;

#pragma unroll
    for (int t = 0; t < TT; t++) DOT_T(0, t, preA[t]);   // dots(chunk 0)

    // ---------------- main: iter c scans(c) while computing dots(c+1) -----
    // (preCur/preNxt swap handled by 2x-unrolled loop body)
#define ITER(C, PRECUR, PRENXT)                                               \
    {   const int nb = (C + 1) & 1;                                           \
        if ((C) + 1 < NCH) {                                                  \
            STAGE(nb);                                                        \
            __syncthreads();          /* su ready + tile(c-1) consumed */     \
            if ((C) + 2 < NCH) PREFETCH(((C) + 2) * TT);                      \
            _Pragma("unroll")                                                 \
            for (int t = 0; t < TT; t++) {                                    \
                DOT_T(nb, t, PRENXT[t]);   /* ILP stream */                   \
                SCAN_T(PRECUR, t);         /* 44-cyc chain, hidden */         \
            }                                                                 \
        } else {                                                              \
            __syncthreads();                                                  \
            _Pragma("unroll")                                                 \
            for (int t = 0; t < TT; t++) SCAN_T(PRECUR, t);                   \
        }                                                                     \
        STORE_TILE(PRECUR);                                                   \
        __syncthreads();              /* tile complete */                     \
        OUTPUT((C) * TT); }

    for (int c = 0; c < NCH; c += 2) {
        ITER(c,     preA, preB);
        ITER(c + 1, preB, preA);
    }
}

extern "C" void kernel_launch(void* const* d_in, const int* in_sizes, int n_in,
                              void* d_out, int out_size) {
    const float* u    = (const float*)d_in[0];
    const float* w_in = (const float*)d_in[1];
    const float* w_hh = (const float*)d_in[2];
    const float* bias = (const float*)d_in[3];
    float* out = (float*)d_out;

    dim3 grid(DST / PTILE, BB);   // (8, 32) = 256 blocks
    esn_kernel<<<grid, PTILE>>>(u, w_in, w_hh, bias, out);
}

// round 9
// speedup vs baseline: 1.3562x; 1.3562x over previous
#include <cuda_runtime.h>
#include <cstdint>

// ESN: out[b,p,l], elementwise-diagonal recurrence.
// v6: dot phase on tensor cores — mma.sync.m16n8k8 tf32 with 3x-split
//     (Ahi*Bhi + Ahi*Blo + Alo*Bhi) for fp32-grade accuracy. W fragments
//     stationary in registers across all 64 chunks. Scan unchanged.
#define BB 32
#define DIN 64
#define DST 1024
#define LL 2048
#define TT 32
#define PTILE 128
#define NCH (LL / TT)
#define TSTR 36   // tile row stride (floats)

__device__ __forceinline__ uint32_t cvt_tf32(float x) {
    uint32_t r; asm("cvt.rna.tf32.f32 %0,%1;" : "=r"(r) : "f"(x)); return r;
}
__device__ __forceinline__ float ex2f(float v) {
    float r; asm("ex2.approx.f32 %0,%1;" : "=f"(r) : "f"(v)); return r;
}
__device__ __forceinline__ float rcpf(float v) {
    float r; asm("rcp.approx.f32 %0,%1;" : "=f"(r) : "f"(v)); return r;
}
__device__ __forceinline__ void mma_tf32(float c[4], const uint32_t a[4],
                                         uint32_t b0, uint32_t b1) {
    asm("mma.sync.aligned.m16n8k8.row.col.f32.tf32.tf32.f32 "
        "{%0,%1,%2,%3}, {%4,%5,%6,%7}, {%8,%9}, {%0,%1,%2,%3};"
        : "+f"(c[0]), "+f"(c[1]), "+f"(c[2]), "+f"(c[3])
        : "r"(a[0]), "r"(a[1]), "r"(a[2]), "r"(a[3]), "r"(b0), "r"(b1));
}

__global__ __launch_bounds__(PTILE, 2) void esn_kernel(
    const float* __restrict__ u,      // [B, DIN, L]
    const float* __restrict__ w_in,   // [DST, DIN]
    const float* __restrict__ w_hh,   // [DST, DST] (diagonal used)
    const float* __restrict__ bias,   // [DST]
    float* __restrict__ out)          // [B, DST, L]
{
    __shared__ __align__(16) float su[TT][68];        // u chunk, [t][h]
    __shared__ __align__(16) float tile[PTILE][TSTR]; // C frags / x outputs

    const int tid  = threadIdx.x;
    const int wid  = tid >> 5;
    const int lane = tid & 31;
    const int gid  = lane >> 2;     // groupID (row offset in mma frags)
    const int tig  = lane & 3;      // thread-in-group (k / col offset)
    const int b    = blockIdx.y;
    const int p0   = blockIdx.x * PTILE;

    const float K2 = 2.8853900817779268f;   // 2*log2(e), folded into W & bias

    // ---- stationary A fragments: W rows for this warp, K2-scaled, split ----
    // warp w covers p rows [p0+32w, p0+32w+32); mt selects the 16-row half.
    uint32_t Ahi[2][8][4], Alo[2][8][4];
#pragma unroll
    for (int mt = 0; mt < 2; mt++) {
#pragma unroll
        for (int ks = 0; ks < 8; ks++) {
            int r0 = p0 + 32 * wid + 16 * mt + gid;
            int k0 = tig + 8 * ks;
            float w00 = w_in[(size_t)r0 * DIN + k0] * K2;
            float w10 = w_in[(size_t)(r0 + 8) * DIN + k0] * K2;
            float w01 = w_in[(size_t)r0 * DIN + k0 + 4] * K2;
            float w11 = w_in[(size_t)(r0 + 8) * DIN + k0 + 4] * K2;
            uint32_t h0 = cvt_tf32(w00), h1 = cvt_tf32(w10);
            uint32_t h2 = cvt_tf32(w01), h3 = cvt_tf32(w11);
            Ahi[mt][ks][0] = h0; Ahi[mt][ks][1] = h1;
            Ahi[mt][ks][2] = h2; Ahi[mt][ks][3] = h3;
            Alo[mt][ks][0] = cvt_tf32(w00 - __uint_as_float(h0));
            Alo[mt][ks][1] = cvt_tf32(w10 - __uint_as_float(h1));
            Alo[mt][ks][2] = cvt_tf32(w01 - __uint_as_float(h2));
            Alo[mt][ks][3] = cvt_tf32(w11 - __uint_as_float(h3));
        }
    }
    // bias (K2-scaled) for this lane's C rows: bb[mt][j] = bias(row gid+8j)
    float bb[2][2];
#pragma unroll
    for (int mt = 0; mt < 2; mt++) {
        bb[mt][0] = bias[p0 + 32 * wid + 16 * mt + gid] * K2;
        bb[mt][1] = bias[p0 + 32 * wid + 16 * mt + gid + 8] * K2;
    }
    // scan constants for chain p = p0 + tid
    const int p = p0 + tid;
    const float d2 = w_hh[(size_t)p * DST + p] * K2;

    const float* ub = u + (size_t)b * DIN * LL;
    float*       ob = out + ((size_t)b * DST + p0) * LL;

    // staging geometry: 4 float4 per thread cover 64h x 32t (transposed)
    const int h0 = (tid + 0 * PTILE) >> 3, t0 = ((tid + 0 * PTILE) & 7) << 2;
    const int h1 = (tid + 1 * PTILE) >> 3, t1 = ((tid + 1 * PTILE) & 7) << 2;
    const int h2 = (tid + 2 * PTILE) >> 3, t2 = ((tid + 2 * PTILE) & 7) << 2;
    const int h3 = (tid + 3 * PTILE) >> 3, t3 = ((tid + 3 * PTILE) & 7) << 2;
    const int orow = tid >> 3, ocol = (tid & 7) << 2;   // output transpose

    float4 g0, g1, g2, g3;

#define PREFETCH(L0)                                                          \
    {   const float* un = ub + (size_t)(L0);                                  \
        g0 = *(const float4*)(un + (size_t)h0 * LL + t0);                     \
        g1 = *(const float4*)(un + (size_t)h1 * LL + t1);                     \
        g2 = *(const float4*)(un + (size_t)h2 * LL + t2);                     \
        g3 = *(const float4*)(un + (size_t)h3 * LL + t3); }

#define STAGE()                                                               \
    {   su[t0+0][h0]=g0.x; su[t0+1][h0]=g0.y; su[t0+2][h0]=g0.z; su[t0+3][h0]=g0.w; \
        su[t1+0][h1]=g1.x; su[t1+1][h1]=g1.y; su[t1+2][h1]=g1.z; su[t1+3][h1]=g1.w; \
        su[t2+0][h2]=g2.x; su[t2+1][h2]=g2.y; su[t2+2][h2]=g2.z; su[t2+3][h2]=g2.w; \
        su[t3+0][h3]=g3.x; su[t3+1][h3]=g3.y; su[t3+2][h3]=g3.z; su[t3+3][h3]=g3.w; }

    // prologue: stage chunk 0
    PREFETCH(0);
    STAGE();

    float x = 0.0f;

    for (int c = 0; c < NCH; c++) {
        __syncthreads();                 // bar A: su staged, tile free
        if (c + 1 < NCH) PREFETCH((c + 1) * TT);   // LDG in flight under mma

        // ===== MMA phase: C[128p x 32t] += Wk2 * u, 3x-tf32 split =====
        float cf[2][4][4];
#pragma unroll
        for (int mt = 0; mt < 2; mt++)
#pragma unroll
            for (int nt = 0; nt < 4; nt++) {
                cf[mt][nt][0] = bb[mt][0]; cf[mt][nt][1] = bb[mt][0];
                cf[mt][nt][2] = bb[mt][1]; cf[mt][nt][3] = bb[mt][1];
            }
#pragma unroll
        for (int nt = 0; nt < 4; nt++) {
            const int n = gid + 8 * nt;       // t-column this lane feeds
#pragma unroll
            for (int ks = 0; ks < 8; ks++) {
                float u0 = su[n][tig + 8 * ks];
                float u1 = su[n][tig + 4 + 8 * ks];
                uint32_t bh0 = cvt_tf32(u0), bh1 = cvt_tf32(u1);
                uint32_t bl0 = cvt_tf32(u0 - __uint_as_float(bh0));
                uint32_t bl1 = cvt_tf32(u1 - __uint_as_float(bh1));
#pragma unroll
                for (int mt = 0; mt < 2; mt++) {
                    mma_tf32(cf[mt][nt], Ahi[mt][ks], bh0, bh1);
                    mma_tf32(cf[mt][nt], Ahi[mt][ks], bl0, bl1);
                    mma_tf32(cf[mt][nt], Alo[mt][ks], bh0, bh1);
                }
            }
        }

        // ===== C frags -> tile (pre2 values, K2*(' dot + bias')) =====
#pragma unroll
        for (int mt = 0; mt < 2; mt++)
#pragma unroll
            for (int nt = 0; nt < 4; nt++) {
                int r0  = 32 * wid + 16 * mt + gid;
                int col = 8 * nt + 2 * tig;
                *(float2*)&tile[r0][col]     = make_float2(cf[mt][nt][0], cf[mt][nt][1]);
                *(float2*)&tile[r0 + 8][col] = make_float2(cf[mt][nt][2], cf[mt][nt][3]);
            }
        __syncwarp();   // tile rows of this warp complete

        // ===== scan: thread tid owns chain p0+tid, 32 steps =====
        {
            float v[TT];
#pragma unroll
            for (int k = 0; k < TT / 4; k++)
                *(float4*)&v[4 * k] = *(const float4*)&tile[tid][4 * k];
#pragma unroll
            for (int t = 0; t < TT; t++) {
                float p2 = fmaf(d2, x, v[t]);
                float e  = ex2f(p2);
                float r  = rcpf(e + 1.0f);
                x = fmaf(0.5f, x, 0.5f) - r;
                v[t] = x;
            }
#pragma unroll
            for (int k = 0; k < TT / 4; k++)
                *(float4*)&tile[tid][4 * k] = *(const float4*)&v[4 * k];
        }
        __syncthreads();                 // bar B: mma done (su free), tile done

        if (c + 1 < NCH) STAGE();        // overwrite su for next chunk

        // ===== coalesced output: 8x (LDS.128 + STG.128) =====
#pragma unroll
        for (int it = 0; it < 8; it++) {
            int row = orow + it * 16;
            float4 vv = *(const float4*)&tile[row][ocol];
            *(float4*)(ob + (size_t)row * LL + c * TT + ocol) = vv;
        }
    }
}

extern "C" void kernel_launch(void* const* d_in, const int* in_sizes, int n_in,
                              void* d_out, int out_size) {
    const float* u    = (const float*)d_in[0];
    const float* w_in = (const float*)d_in[1];
    const float* w_hh = (const float*)d_in[2];
    const float* bias = (const float*)d_in[3];
    float* out = (float*)d_out;

    dim3 grid(DST / PTILE, BB);   // (8, 32) = 256 blocks
    esn_kernel<<<grid, PTILE>>>(u, w_in, w_hh, bias, out);
}